// round 7
// baseline (speedup 1.0000x reference)
#include <cuda_runtime.h>
#include <math.h>
#include <float.h>

#define B   8
#define L   256
#define H   128
#define NH  4
#define D   32
#define NB  2
#define NROWS (B*L)

// ---------------- scratch (device globals; no allocation allowed) ------------
__device__ float g_x  [NROWS*H];
__device__ float g_q  [NROWS*H];
__device__ float g_Q  [NROWS*H];      // pre-scaled by log2(e)/sqrt(D)
__device__ float g_K  [NROWS*H];
__device__ float g_V  [NROWS*H];
__device__ float g_QA1[NROWS*NH*H];   // pre-scaled by log2(e)/sqrt(D)

__device__ __forceinline__ float dot4(float4 a, float4 b) {
    return a.x*b.x + a.y*b.y + a.z*b.z + a.w*b.w;
}

// ---------------- LN1 + QKV + QA1 projections (fused), 4 rows/CTA ------------
#define RQ 4
__global__ __launch_bounds__(128)
void qkv_kernel(const float* __restrict__ ext_src, int use_ext,
                const float* __restrict__ lng, const float* __restrict__ lnb,
                const float* __restrict__ Qw, const float* __restrict__ Qb,
                const float* __restrict__ Kw, const float* __restrict__ Kb,
                const float* __restrict__ Vw, const float* __restrict__ Vb,
                const float* __restrict__ WA1)
{
    __shared__ __align__(16) float qs[RQ][H];
    __shared__ __align__(16) float Qs[RQ][H];
    __shared__ float stat[RQ][2];
    int t = threadIdx.x;
    int row0 = blockIdx.x * RQ;
    int w = t >> 5, lane = t & 31;

    float v[RQ];
    #pragma unroll
    for (int r = 0; r < RQ; r++) {
        v[r] = use_ext ? ext_src[(row0+r)*H + t] : g_x[(row0+r)*H + t];
        qs[r][t] = v[r];
    }
    __syncthreads();

    // warp w reduces row w
    {
        float4 a = *(const float4*)(&qs[w][lane*4]);
        float s  = a.x + a.y + a.z + a.w;
        float sq = a.x*a.x + a.y*a.y + a.z*a.z + a.w*a.w;
        #pragma unroll
        for (int o = 16; o; o >>= 1) {
            s  += __shfl_xor_sync(0xffffffffu, s,  o);
            sq += __shfl_xor_sync(0xffffffffu, sq, o);
        }
        if (lane == 0) {
            float mean = s * (1.0f/H);
            float var  = sq * (1.0f/H) - mean*mean;
            stat[w][0] = mean;
            stat[w][1] = rsqrtf(var + 1e-8f);
        }
    }
    __syncthreads();

    float gam = lng[t], bet = lnb[t];
    #pragma unroll
    for (int r = 0; r < RQ; r++) {
        float q = (v[r] - stat[r][0]) * stat[r][1] * gam + bet;
        qs[r][t] = q;
        g_q[(row0+r)*H + t] = q;
    }
    __syncthreads();

    float aq[RQ], ak[RQ], av[RQ];
    #pragma unroll
    for (int r = 0; r < RQ; r++) { aq[r] = 0.f; ak[r] = 0.f; av[r] = 0.f; }
    const float* qwr = Qw + t*H;
    const float* kwr = Kw + t*H;
    const float* vwr = Vw + t*H;
    #pragma unroll 4
    for (int k = 0; k < H; k += 4) {
        float4 wq = *(const float4*)(qwr + k);
        float4 wk = *(const float4*)(kwr + k);
        float4 wv = *(const float4*)(vwr + k);
        #pragma unroll
        for (int r = 0; r < RQ; r++) {
            float4 q4 = *(const float4*)(&qs[r][k]);
            aq[r] += q4.x*wq.x + q4.y*wq.y + q4.z*wq.z + q4.w*wq.w;
            ak[r] += q4.x*wk.x + q4.y*wk.y + q4.z*wk.z + q4.w*wk.w;
            av[r] += q4.x*wv.x + q4.y*wv.y + q4.z*wv.z + q4.w*wv.w;
        }
    }
    // 1/sqrt(32) * log2(e): fixed-base exp2 softmax downstream
    const float rs = 0.17677669529663687f * 1.4426950408889634f;
    float bq = Qb[t], bk = Kb[t], bv = Vb[t];
    #pragma unroll
    for (int r = 0; r < RQ; r++) {
        float Qv = (aq[r] + bq) * rs;
        Qs[r][t] = Qv;
        g_Q[(row0+r)*H + t] = Qv;
        g_K[(row0+r)*H + t] = ak[r] + bk;
        g_V[(row0+r)*H + t] = av[r] + bv;
    }
    __syncthreads();

    #pragma unroll
    for (int h = 0; h < NH; h++) {
        float a[RQ];
        #pragma unroll
        for (int r = 0; r < RQ; r++) a[r] = 0.f;
        const float* w1 = WA1 + h*D*H + t;
        #pragma unroll 2
        for (int dd = 0; dd < D; dd += 4) {
            float w0 = w1[(dd+0)*H];
            float wA = w1[(dd+1)*H];
            float wB = w1[(dd+2)*H];
            float wC = w1[(dd+3)*H];
            #pragma unroll
            for (int r = 0; r < RQ; r++) {
                float4 q4 = *(const float4*)(&Qs[r][h*D + dd]);
                a[r] += q4.x*w0 + q4.y*wA + q4.z*wB + q4.w*wC;
            }
        }
        #pragma unroll
        for (int r = 0; r < RQ; r++)
            g_QA1[((row0+r)*NH + h)*H + t] = a[r];
    }
}

// ---------------- Attention v4: warps partition j, all heads per warp --------
// Warp w handles j = 4*tI + w. Each tm row is read ONCE per CTA (4 wavefronts)
// instead of once per head (16). Scores for all 4 heads are reduced together
// with a 4-component butterfly. Fixed-base exp2, no online max (scores O(1)).
__global__ __launch_bounds__(128)
void attn_kernel(const float* __restrict__ tm,
                 const unsigned char* __restrict__ tmask,
                 const float* __restrict__ WA2)
{
    __shared__ __align__(16) float sSp[4][NH][H];   // per-warp accS partials
    __shared__ __align__(16) float sVp[4][H];       // per-warp accV partials
    __shared__ float ssum[4][NH];
    __shared__ __align__(16) float sS[NH][H];
    __shared__ __align__(16) float sVt[H];

    int row  = blockIdx.x;
    int b    = row >> 8;          // L = 256
    int i    = row & (L-1);
    int lane = threadIdx.x & 31;
    int w    = threadIdx.x >> 5;  // warp = j-phase
    int o    = lane >> 3;         // lane's head (for K/V/Q dims 4*lane..)

    // per-lane slices (dims 4*lane .. 4*lane+3)
    const float* qaB = g_QA1 + (size_t)row*NH*H + lane*4;
    float4 qa0 = *(const float4*)(qaB);
    float4 qa1 = *(const float4*)(qaB + H);
    float4 qa2 = *(const float4*)(qaB + 2*H);
    float4 qa3 = *(const float4*)(qaB + 3*H);
    float4 q4  = *(const float4*)(g_Q + row*H + lane*4);

    bool rmask = tmask[row] != 0;
    int  limit = rmask ? (L-1) : i;
    int  nt    = (limit >> 2) + 1;

    const float* tmp = tm  + (size_t)row * L * H + (size_t)w * H + lane*4;
    const float* Kp  = g_K + (b*L + w)*H + lane*4;
    const float* Vp  = g_V + (b*L + w)*H + lane*4;

    float4 sum  = make_float4(0.f,0.f,0.f,0.f);   // per-head weight sums
    float4 accV = make_float4(0.f,0.f,0.f,0.f);   // lane's 4 dims (head o)
    float4 aS0  = make_float4(0.f,0.f,0.f,0.f);   // accS for head 0, lane dims
    float4 aS1  = make_float4(0.f,0.f,0.f,0.f);
    float4 aS2  = make_float4(0.f,0.f,0.f,0.f);
    float4 aS3  = make_float4(0.f,0.f,0.f,0.f);

    #pragma unroll 2
    for (int tI = 0; tI < nt; tI++) {
        int j = tI*4 + w;
        float4 t4 = __ldcs((const float4*)tmp);
        float4 k4 = *(const float4*)Kp;
        float4 v4 = *(const float4*)Vp;
        tmp += 4*H; Kp += 4*H; Vp += 4*H;

        // per-head partial scores from this lane's 4 dims
        float s0 = dot4(qa0, t4);
        float s1 = dot4(qa1, t4);
        float s2 = dot4(qa2, t4);
        float s3 = dot4(qa3, t4);
        float qk = dot4(q4, k4);
        s0 += (o == 0) ? qk : 0.f;
        s1 += (o == 1) ? qk : 0.f;
        s2 += (o == 2) ? qk : 0.f;
        s3 += (o == 3) ? qk : 0.f;

        #pragma unroll
        for (int off = 1; off <= 16; off <<= 1) {
            s0 += __shfl_xor_sync(0xffffffffu, s0, off);
            s1 += __shfl_xor_sync(0xffffffffu, s1, off);
            s2 += __shfl_xor_sync(0xffffffffu, s2, off);
            s3 += __shfl_xor_sync(0xffffffffu, s3, off);
        }

        bool valid = (j <= limit);
        float w0 = valid ? exp2f(rmask ? 0.f : s0) : 0.f;
        float w1 = valid ? exp2f(rmask ? 0.f : s1) : 0.f;
        float w2 = valid ? exp2f(rmask ? 0.f : s2) : 0.f;
        float w3 = valid ? exp2f(rmask ? 0.f : s3) : 0.f;

        sum.x += w0; sum.y += w1; sum.z += w2; sum.w += w3;
        float wo = (o == 0) ? w0 : ((o == 1) ? w1 : ((o == 2) ? w2 : w3));
        accV.x += wo*v4.x; accV.y += wo*v4.y; accV.z += wo*v4.z; accV.w += wo*v4.w;
        aS0.x += w0*t4.x; aS0.y += w0*t4.y; aS0.z += w0*t4.z; aS0.w += w0*t4.w;
        aS1.x += w1*t4.x; aS1.y += w1*t4.y; aS1.z += w1*t4.z; aS1.w += w1*t4.w;
        aS2.x += w2*t4.x; aS2.y += w2*t4.y; aS2.z += w2*t4.z; aS2.w += w2*t4.w;
        aS3.x += w3*t4.x; aS3.y += w3*t4.y; aS3.z += w3*t4.z; aS3.w += w3*t4.w;
    }

    // stash per-warp partials
    *(float4*)(&sSp[w][0][lane*4]) = aS0;
    *(float4*)(&sSp[w][1][lane*4]) = aS1;
    *(float4*)(&sSp[w][2][lane*4]) = aS2;
    *(float4*)(&sSp[w][3][lane*4]) = aS3;
    *(float4*)(&sVp[w][lane*4]) = accV;
    if (lane == 0) {
        ssum[w][0] = sum.x; ssum[w][1] = sum.y;
        ssum[w][2] = sum.z; ssum[w][3] = sum.w;
    }
    __syncthreads();

    // combine across warps: thread t handles dim t
    {
        int t = threadIdx.x;
        #pragma unroll
        for (int h = 0; h < NH; h++)
            sS[h][t] = sSp[0][h][t] + sSp[1][h][t] + sSp[2][h][t] + sSp[3][h][t];
        sVt[t] = sVp[0][t] + sVp[1][t] + sVp[2][t] + sVp[3][t];
    }
    __syncthreads();

    // epilogue: warp h -> out dims of head h
    {
        int h = w;
        float tot = ssum[0][h] + ssum[1][h] + ssum[2][h] + ssum[3][h];
        const float* wr = WA2 + (h*D + lane)*H;
        float a0 = 0.f, a1 = 0.f;
        #pragma unroll
        for (int k = 0; k < H; k += 8) {
            float4 w0 = *(const float4*)(wr + k);
            float4 s0 = *(const float4*)(&sS[h][k]);
            float4 w1 = *(const float4*)(wr + k + 4);
            float4 s1 = *(const float4*)(&sS[h][k+4]);
            a0 += w0.x*s0.x + w0.y*s0.y + w0.z*s0.z + w0.w*s0.w;
            a1 += w1.x*s1.x + w1.y*s1.y + w1.z*s1.z + w1.w*s1.w;
        }
        float out = (sVt[h*D + lane] + a0 + a1) / tot;
        int idx = row*H + h*D + lane;
        g_x[idx] = g_q[idx] + out;
    }
}

// ---------------- LN2 + FFN + mask (+ optional fused final LN) ---------------
#define FR 4
__global__ __launch_bounds__(128)
void ffn_kernel(const float* __restrict__ lng, const float* __restrict__ lnb,
                const float* __restrict__ c1w, const float* __restrict__ c1b,
                const float* __restrict__ c2w, const float* __restrict__ c2b,
                const unsigned char* __restrict__ tmask,
                float* __restrict__ dst,             // non-null => fused final LN
                const float* __restrict__ lnfg, const float* __restrict__ lnfb)
{
    __shared__ __align__(16) float ys[FR][H];
    __shared__ __align__(16) float hs[FR][H];
    __shared__ float stat[FR][2];
    int t = threadIdx.x;
    int row0 = blockIdx.x * FR;
    int w = t >> 5, lane = t & 31;

    float v[FR];
    #pragma unroll
    for (int r = 0; r < FR; r++) {
        v[r] = g_x[(row0+r)*H + t];
        ys[r][t] = v[r];
    }
    __syncthreads();

    {
        float4 a = *(const float4*)(&ys[w][lane*4]);
        float s  = a.x + a.y + a.z + a.w;
        float sq = a.x*a.x + a.y*a.y + a.z*a.z + a.w*a.w;
        #pragma unroll
        for (int o = 16; o; o >>= 1) {
            s  += __shfl_xor_sync(0xffffffffu, s,  o);
            sq += __shfl_xor_sync(0xffffffffu, sq, o);
        }
        if (lane == 0) {
            float mean = s * (1.0f/H);
            float var  = sq * (1.0f/H) - mean*mean;
            stat[w][0] = mean;
            stat[w][1] = rsqrtf(var + 1e-8f);
        }
    }
    __syncthreads();

    float gam = lng[t], bet = lnb[t];
    float y[FR];
    #pragma unroll
    for (int r = 0; r < FR; r++) {
        y[r] = (v[r] - stat[r][0]) * stat[r][1] * gam + bet;
        ys[r][t] = y[r];
    }
    __syncthreads();

    float acc[FR];
    #pragma unroll
    for (int r = 0; r < FR; r++) acc[r] = 0.f;
    const float* w1r = c1w + t*H;
    #pragma unroll 4
    for (int k = 0; k < H; k += 4) {
        float4 ww = *(const float4*)(w1r + k);
        #pragma unroll
        for (int r = 0; r < FR; r++) {
            float4 yy = *(const float4*)(&ys[r][k]);
            acc[r] += yy.x*ww.x + yy.y*ww.y + yy.z*ww.z + yy.w*ww.w;
        }
    }
    float b1 = c1b[t];
    #pragma unroll
    for (int r = 0; r < FR; r++) hs[r][t] = fmaxf(acc[r] + b1, 0.f);
    __syncthreads();

    #pragma unroll
    for (int r = 0; r < FR; r++) acc[r] = 0.f;
    const float* w2r = c2w + t*H;
    #pragma unroll 4
    for (int k = 0; k < H; k += 4) {
        float4 ww = *(const float4*)(w2r + k);
        #pragma unroll
        for (int r = 0; r < FR; r++) {
            float4 hh = *(const float4*)(&hs[r][k]);
            acc[r] += hh.x*ww.x + hh.y*ww.y + hh.z*ww.z + hh.w*ww.w;
        }
    }
    float b2 = c2b[t];
    float xo[FR];
    #pragma unroll
    for (int r = 0; r < FR; r++) {
        float keep = tmask[row0+r] ? 0.f : 1.f;
        xo[r] = (acc[r] + b2 + y[r]) * keep;
    }

    if (dst == nullptr) {
        #pragma unroll
        for (int r = 0; r < FR; r++) g_x[(row0+r)*H + t] = xo[r];
        return;
    }

    // fused final LayerNorm
    #pragma unroll
    for (int r = 0; r < FR; r++) ys[r][t] = xo[r];
    __syncthreads();
    {
        float4 a = *(const float4*)(&ys[w][lane*4]);
        float s  = a.x + a.y + a.z + a.w;
        float sq = a.x*a.x + a.y*a.y + a.z*a.z + a.w*a.w;
        #pragma unroll
        for (int o = 16; o; o >>= 1) {
            s  += __shfl_xor_sync(0xffffffffu, s,  o);
            sq += __shfl_xor_sync(0xffffffffu, sq, o);
        }
        if (lane == 0) {
            float mean = s * (1.0f/H);
            float var  = sq * (1.0f/H) - mean*mean;
            stat[w][0] = mean;
            stat[w][1] = rsqrtf(var + 1e-8f);
        }
    }
    __syncthreads();
    float fg = lnfg[t], fb = lnfb[t];
    #pragma unroll
    for (int r = 0; r < FR; r++)
        dst[(row0+r)*H + t] = (xo[r] - stat[r][0]) * stat[r][1] * fg + fb;
}

// ---------------- launch -----------------------------------------------------
extern "C" void kernel_launch(void* const* d_in, const int* in_sizes, int n_in,
                              void* d_out, int out_size)
{
    const float*         seqs  = (const float*)d_in[0];
    const unsigned char* tmask = (const unsigned char*)d_in[1];
    const float*         tm    = (const float*)d_in[2];
    const float* Qw  = (const float*)d_in[3];
    const float* Qb  = (const float*)d_in[4];
    const float* Kw  = (const float*)d_in[5];
    const float* Kb  = (const float*)d_in[6];
    const float* Vw  = (const float*)d_in[7];
    const float* Vb  = (const float*)d_in[8];
    const float* WA1 = (const float*)d_in[9];
    const float* WA2 = (const float*)d_in[10];
    const float* ln1g = (const float*)d_in[11];
    const float* ln1b = (const float*)d_in[12];
    const float* ln2g = (const float*)d_in[13];
    const float* ln2b = (const float*)d_in[14];
    const float* c1w  = (const float*)d_in[15];
    const float* c1b  = (const float*)d_in[16];
    const float* c2w  = (const float*)d_in[17];
    const float* c2b  = (const float*)d_in[18];
    const float* lnfg = (const float*)d_in[19];
    const float* lnfb = (const float*)d_in[20];
    float* out = (float*)d_out;

    for (int blk = 0; blk < NB; blk++) {
        qkv_kernel<<<NROWS/RQ, 128>>>(seqs, blk == 0 ? 1 : 0,
                                      ln1g + blk*H, ln1b + blk*H,
                                      Qw + blk*H*H, Qb + blk*H,
                                      Kw + blk*H*H, Kb + blk*H,
                                      Vw + blk*H*H, Vb + blk*H,
                                      WA1 + blk*H*H);
        attn_kernel<<<NROWS, 128>>>(tm, tmask, WA2 + blk*H*H);
        ffn_kernel<<<NROWS/FR, 128>>>(ln2g + blk*H, ln2b + blk*H,
                                      c1w + blk*H*H, c1b + blk*H,
                                      c2w + blk*H*H, c2b + blk*H,
                                      tmask,
                                      blk == NB-1 ? out : nullptr,
                                      lnfg, lnfb);
    }
}